// round 2
// baseline (speedup 1.0000x reference)
#include <cuda_runtime.h>
#include <cuda_bf16.h>
#include <cstdint>

#define N_NODES_MAX 100000

// Scratch accumulators: [node][4] = {x, y, z, (count or 0)} — 16B aligned for v4 red.
__device__ __align__(16) float g_facc[N_NODES_MAX * 4];
__device__ __align__(16) float g_tacc[N_NODES_MAX * 4];
__device__ __align__(16) float g_cacc[N_NODES_MAX * 4];

// ---------------------------------------------------------------------------
// Zero the accumulators
// ---------------------------------------------------------------------------
__global__ void zero_kernel(int n4) {
    int i = blockIdx.x * blockDim.x + threadIdx.x;
    float4 z = make_float4(0.f, 0.f, 0.f, 0.f);
    if (i < n4) {
        reinterpret_cast<float4*>(g_facc)[i] = z;
        reinterpret_cast<float4*>(g_tacc)[i] = z;
        reinterpret_cast<float4*>(g_cacc)[i] = z;
    }
}

// ---------------------------------------------------------------------------
// Edge scatter: per-edge vector reduction atomics into node accumulators
// ---------------------------------------------------------------------------
__device__ __forceinline__ void red4(float* p, float x, float y, float z, float w) {
    asm volatile("red.global.add.v4.f32 [%0], {%1,%2,%3,%4};"
                 :: "l"(p), "f"(x), "f"(y), "f"(z), "f"(w) : "memory");
}

__global__ void __launch_bounds__(256)
scatter_kernel(const int* __restrict__ edge_index,
               const float* __restrict__ ef,
               const float* __restrict__ et,
               const float* __restrict__ ec,
               int E) {
    int e = blockIdx.x * blockDim.x + threadIdx.x;
    if (e >= E) return;
    int r = edge_index[E + e];   // receivers = edge_index[1]
    float fx = ef[e * 3 + 0], fy = ef[e * 3 + 1], fz = ef[e * 3 + 2];
    float tx = et[e * 3 + 0], ty = et[e * 3 + 1], tz = et[e * 3 + 2];
    float cx = ec[e * 3 + 0], cy = ec[e * 3 + 1], cz = ec[e * 3 + 2];
    red4(&g_facc[r * 4], fx, fy, fz, 1.0f);   // 4th lane = edge count
    red4(&g_tacc[r * 4], tx, ty, tz, 0.0f);
    red4(&g_cacc[r * 4], cx, cy, cz, 0.0f);
}

// ---------------------------------------------------------------------------
// Fused node kernel: 4 MLPs (layer1 128x128 GEMM per MLP, fused layer2)
// + final combine writing the three [N,3] outputs.
// Block: 256 threads, 128 nodes. Thread tile: 8 nodes x 8 hidden.
// ---------------------------------------------------------------------------
#define BM 128
#define XS_PITCH 130           // pad so 2 node-rows 8 apart hit distinct banks
#define SMEM_FLOATS (BM * XS_PITCH + 128 * 128 + BM * 8)
#define SMEM_BYTES  (SMEM_FLOATS * 4)

__global__ void __launch_bounds__(256, 1)
mlp_combine_kernel(const float* __restrict__ X,        // [N,128]
                   const float* __restrict__ vel,      // [N,3]
                   const float* __restrict__ mW1, const float* __restrict__ mb1,
                   const float* __restrict__ mW2, const float* __restrict__ mb2,
                   const float* __restrict__ iW1, const float* __restrict__ ib1,
                   const float* __restrict__ iW2, const float* __restrict__ ib2,
                   const float* __restrict__ eW1, const float* __restrict__ eb1,
                   const float* __restrict__ eW2, const float* __restrict__ eb2,
                   const float* __restrict__ vW1, const float* __restrict__ vb1,
                   const float* __restrict__ vW2, const float* __restrict__ vb2,
                   float* __restrict__ out, int N) {
    extern __shared__ float smem[];
    float* Xs  = smem;                       // [128][130] node-major
    float* Ws  = smem + BM * XS_PITCH;       // [128][128] k-major
    float* Ysm = Ws + 128 * 128;             // [128][8] per-node outputs

    const int tid = threadIdx.x;
    const int tc = tid & 15;                 // 0..15 (hidden tile col)
    const int tr = tid >> 4;                 // 0..15 (node tile row)
    const int nodeBase = blockIdx.x * BM;

    // ---- Load X tile (coalesced), zero-pad OOB nodes ----
    #pragma unroll
    for (int it = 0; it < 16; ++it) {
        int idx4 = tid + it * 256;           // 0..4095 float4s
        int node = idx4 >> 5;                // /32
        int c4   = idx4 & 31;
        float4 v = make_float4(0.f, 0.f, 0.f, 0.f);
        int g = nodeBase + node;
        if (g < N) v = reinterpret_cast<const float4*>(X)[g * 32 + c4];
        float* dst = &Xs[node * XS_PITCH + c4 * 4];
        dst[0] = v.x; dst[1] = v.y; dst[2] = v.z; dst[3] = v.w;
    }
    for (int i = tid; i < BM * 8; i += 256) Ysm[i] = 0.f;

    const float* W1s[4] = {mW1, iW1, eW1, vW1};
    const float* b1s[4] = {mb1, ib1, eb1, vb1};
    const float* W2s[4] = {mW2, iW2, eW2, vW2};
    const int ncol[4] = {1, 1, 3, 1};
    const int slot[4] = {0, 1, 2, 5};

    for (int j = 0; j < 4; ++j) {
        __syncthreads();  // Xs ready (1st iter) / prev GEMM done reading Ws
        // ---- Load W1_j tile (16K floats, float4 coalesced) ----
        const float4* Wg = reinterpret_cast<const float4*>(W1s[j]);
        #pragma unroll
        for (int it = 0; it < 16; ++it) {
            int idx4 = tid + it * 256;
            reinterpret_cast<float4*>(Ws)[idx4] = Wg[idx4];
        }
        __syncthreads();

        // ---- GEMM 128x128x128, 8x8 register tile ----
        float acc[8][8];
        #pragma unroll
        for (int i = 0; i < 8; ++i)
            #pragma unroll
            for (int jj = 0; jj < 8; ++jj) acc[i][jj] = 0.f;

        #pragma unroll 4
        for (int k = 0; k < 128; ++k) {
            float a[8], b[8];
            #pragma unroll
            for (int i = 0; i < 8; ++i) a[i] = Xs[(tr * 8 + i) * XS_PITCH + k];
            float4 b0 = *reinterpret_cast<const float4*>(&Ws[k * 128 + tc * 8]);
            float4 b1 = *reinterpret_cast<const float4*>(&Ws[k * 128 + tc * 8 + 4]);
            b[0] = b0.x; b[1] = b0.y; b[2] = b0.z; b[3] = b0.w;
            b[4] = b1.x; b[5] = b1.y; b[6] = b1.z; b[7] = b1.w;
            #pragma unroll
            for (int i = 0; i < 8; ++i)
                #pragma unroll
                for (int jj = 0; jj < 8; ++jj)
                    acc[i][jj] = fmaf(a[i], b[jj], acc[i][jj]);
        }

        // ---- Fused layer 2: relu(H+b1) @ W2, reduce into Ysm ----
        const int nc = ncol[j], sl = slot[j];
        const float* b1p = b1s[j];
        const float* W2p = W2s[j];
        float bb1[8], w2[8][3];
        #pragma unroll
        for (int jj = 0; jj < 8; ++jj) {
            int h = tc * 8 + jj;
            bb1[jj] = b1p[h];
            for (int d = 0; d < 3; ++d)
                w2[jj][d] = (d < nc) ? W2p[h * nc + d] : 0.f;
        }
        #pragma unroll
        for (int i = 0; i < 8; ++i) {
            float p0 = 0.f, p1 = 0.f, p2 = 0.f;
            #pragma unroll
            for (int jj = 0; jj < 8; ++jj) {
                float v = fmaxf(acc[i][jj] + bb1[jj], 0.f);
                p0 = fmaf(v, w2[jj][0], p0);
                p1 = fmaf(v, w2[jj][1], p1);
                p2 = fmaf(v, w2[jj][2], p2);
            }
            atomicAdd(&Ysm[(tr * 8 + i) * 8 + sl], p0);
            if (nc == 3) {
                atomicAdd(&Ysm[(tr * 8 + i) * 8 + sl + 1], p1);
                atomicAdd(&Ysm[(tr * 8 + i) * 8 + sl + 2], p2);
            }
        }
    }
    __syncthreads();

    // ---- Combine: one thread per node ----
    if (tid < BM) {
        int g = nodeBase + tid;
        if (g < N) {
            float invm = Ysm[tid * 8 + 0] + mb2[0];
            float invi = Ysm[tid * 8 + 1] + ib2[0];
            float e0 = Ysm[tid * 8 + 2] + eb2[0];
            float e1 = Ysm[tid * 8 + 3] + eb2[1];
            float e2 = Ysm[tid * 8 + 4] + eb2[2];
            float vs = Ysm[tid * 8 + 5] + vb2[0];

            float4 F = *reinterpret_cast<float4*>(&g_facc[g * 4]);
            float4 T = *reinterpret_cast<float4*>(&g_tacc[g * 4]);
            float4 C = *reinterpret_cast<float4*>(&g_cacc[g * 4]);
            float cnt = fmaxf(F.w, 1.0f);
            float inv_cnt = 1.0f / cnt;

            float vx = vel[g * 3 + 0], vy = vel[g * 3 + 1], vz = vel[g * 3 + 2];
            int N3 = N * 3;
            // delta_velocity
            out[g * 3 + 0] = invm * F.x;
            out[g * 3 + 1] = invm * F.y;
            out[g * 3 + 2] = invm * F.z;
            // delta_angular_velocity
            out[N3 + g * 3 + 0] = invi * T.x;
            out[N3 + g * 3 + 1] = invi * T.y;
            out[N3 + g * 3 + 2] = invi * T.z;
            // displacement
            out[2 * N3 + g * 3 + 0] = (vx + e0) * vs + C.x * inv_cnt;
            out[2 * N3 + g * 3 + 1] = (vy + e1) * vs + C.y * inv_cnt;
            out[2 * N3 + g * 3 + 2] = (vz + e2) * vs + C.z * inv_cnt;
        }
    }
}

// ---------------------------------------------------------------------------
extern "C" void kernel_launch(void* const* d_in, const int* in_sizes, int n_in,
                              void* d_out, int out_size) {
    const int*   edge_index = (const int*)  d_in[0];
    const float* node_latent= (const float*)d_in[1];
    const float* vel        = (const float*)d_in[2];
    const float* ef         = (const float*)d_in[3];
    const float* et         = (const float*)d_in[4];
    const float* ec         = (const float*)d_in[5];
    const float* mW1 = (const float*)d_in[6];  const float* mb1 = (const float*)d_in[7];
    const float* mW2 = (const float*)d_in[8];  const float* mb2 = (const float*)d_in[9];
    const float* iW1 = (const float*)d_in[10]; const float* ib1 = (const float*)d_in[11];
    const float* iW2 = (const float*)d_in[12]; const float* ib2 = (const float*)d_in[13];
    const float* eW1 = (const float*)d_in[14]; const float* eb1 = (const float*)d_in[15];
    const float* eW2 = (const float*)d_in[16]; const float* eb2 = (const float*)d_in[17];
    const float* vW1 = (const float*)d_in[18]; const float* vb1 = (const float*)d_in[19];
    const float* vW2 = (const float*)d_in[20]; const float* vb2 = (const float*)d_in[21];
    float* out = (float*)d_out;

    int E = in_sizes[0] / 2;
    int N = in_sizes[1] / 128;

    int n4 = N;  // N float4 entries per accumulator array
    zero_kernel<<<(n4 + 255) / 256, 256>>>(n4);

    scatter_kernel<<<(E + 255) / 256, 256>>>(edge_index, ef, et, ec, E);

    cudaFuncSetAttribute(mlp_combine_kernel,
                         cudaFuncAttributeMaxDynamicSharedMemorySize, SMEM_BYTES);
    mlp_combine_kernel<<<(N + BM - 1) / BM, 256, SMEM_BYTES>>>(
        node_latent, vel,
        mW1, mb1, mW2, mb2,
        iW1, ib1, iW2, ib2,
        eW1, eb1, eW2, eb2,
        vW1, vb1, vW2, vb2,
        out, N);
}

// round 5
// speedup vs baseline: 2.0788x; 2.0788x over previous
#include <cuda_runtime.h>
#include <cuda_bf16.h>
#include <cstdint>

#define N_NODES_MAX 100000

// Scratch accumulators: [node][4] = {x, y, z, (count or 0)} — 16B aligned for v4 red.
__device__ __align__(16) float g_facc[N_NODES_MAX * 4];
__device__ __align__(16) float g_tacc[N_NODES_MAX * 4];
__device__ __align__(16) float g_cacc[N_NODES_MAX * 4];

// ---------------------------------------------------------------------------
// Zero the accumulators
// ---------------------------------------------------------------------------
__global__ void zero_kernel(int n4) {
    int i = blockIdx.x * blockDim.x + threadIdx.x;
    float4 z = make_float4(0.f, 0.f, 0.f, 0.f);
    if (i < n4) {
        reinterpret_cast<float4*>(g_facc)[i] = z;
        reinterpret_cast<float4*>(g_tacc)[i] = z;
        reinterpret_cast<float4*>(g_cacc)[i] = z;
    }
}

// ---------------------------------------------------------------------------
// Edge scatter: per-edge vector reduction atomics into node accumulators
// ---------------------------------------------------------------------------
__device__ __forceinline__ void red4(float* p, float x, float y, float z, float w) {
    asm volatile("red.global.add.v4.f32 [%0], {%1,%2,%3,%4};"
                 :: "l"(p), "f"(x), "f"(y), "f"(z), "f"(w) : "memory");
}

__global__ void __launch_bounds__(256)
scatter_kernel(const int* __restrict__ edge_index,
               const float* __restrict__ ef,
               const float* __restrict__ et,
               const float* __restrict__ ec,
               int E) {
    int e = blockIdx.x * blockDim.x + threadIdx.x;
    if (e >= E) return;
    int r = edge_index[E + e];   // receivers = edge_index[1]
    float fx = ef[e * 3 + 0], fy = ef[e * 3 + 1], fz = ef[e * 3 + 2];
    float tx = et[e * 3 + 0], ty = et[e * 3 + 1], tz = et[e * 3 + 2];
    float cx = ec[e * 3 + 0], cy = ec[e * 3 + 1], cz = ec[e * 3 + 2];
    red4(&g_facc[r * 4], fx, fy, fz, 1.0f);   // 4th lane = edge count
    red4(&g_tacc[r * 4], tx, ty, tz, 0.0f);
    red4(&g_cacc[r * 4], cx, cy, cz, 0.0f);
}

// ===========================================================================
// mma.sync helpers (sm_80+ PTX — works on plain sm_100 target)
// ===========================================================================
__device__ __forceinline__ uint32_t smem_u32(const void* p) {
    uint32_t a;
    asm("{ .reg .u64 t; cvta.to.shared.u64 t, %1; cvt.u32.u64 %0, t; }" : "=r"(a) : "l"(p));
    return a;
}

__device__ __forceinline__ void ldsm_x4(uint32_t& r0, uint32_t& r1, uint32_t& r2, uint32_t& r3,
                                        uint32_t addr) {
    asm volatile("ldmatrix.sync.aligned.m8n8.x4.shared.b16 {%0,%1,%2,%3}, [%4];"
                 : "=r"(r0), "=r"(r1), "=r"(r2), "=r"(r3) : "r"(addr));
}
__device__ __forceinline__ void ldsm_x2t(uint32_t& r0, uint32_t& r1, uint32_t addr) {
    asm volatile("ldmatrix.sync.aligned.m8n8.x2.trans.shared.b16 {%0,%1}, [%2];"
                 : "=r"(r0), "=r"(r1) : "r"(addr));
}
__device__ __forceinline__ void mma_bf16(float* d, const uint32_t* a, const uint32_t* b) {
    asm volatile(
        "mma.sync.aligned.m16n8k16.row.col.f32.bf16.bf16.f32 "
        "{%0,%1,%2,%3}, {%4,%5,%6,%7}, {%8,%9}, {%0,%1,%2,%3};"
        : "+f"(d[0]), "+f"(d[1]), "+f"(d[2]), "+f"(d[3])
        : "r"(a[0]), "r"(a[1]), "r"(a[2]), "r"(a[3]), "r"(b[0]), "r"(b[1]));
}

// ---------------------------------------------------------------------------
// SMEM layout (bytes). Tiles are [128][PITCH] bf16, PITCH=136
// (row stride 272B = 68 words ≡ 4 mod 32 banks -> ldmatrix conflict-free).
// ---------------------------------------------------------------------------
#define PITCH 136
#define TILE_BYTES (128 * PITCH * 2)    // 34816
#define XHI_OFF 0
#define XLO_OFF (XHI_OFF + TILE_BYTES)
#define WHI_OFF (XLO_OFF + TILE_BYTES)
#define WLO_OFF (WHI_OFF + TILE_BYTES)
#define YSM_OFF (WLO_OFF + TILE_BYTES)           // 128*8 floats
#define PAR_OFF (YSM_OFF + 128 * 8 * 4)
#define PAR_FLOATS 1288
#define SMEM_TOTAL (PAR_OFF + PAR_FLOATS * 4)    // ~148.6 KB

// ---------------------------------------------------------------------------
// Fused node kernel: split-bf16 mma.sync layer-1 GEMM + fused layer-2 epilogue
// ---------------------------------------------------------------------------
__global__ void __launch_bounds__(256, 1)
mlp_mma_kernel(const float* __restrict__ X,        // [N,128]
               const float* __restrict__ vel,      // [N,3]
               const float* __restrict__ mW1, const float* __restrict__ mb1,
               const float* __restrict__ mW2, const float* __restrict__ mb2,
               const float* __restrict__ iW1, const float* __restrict__ ib1,
               const float* __restrict__ iW2, const float* __restrict__ ib2,
               const float* __restrict__ eW1, const float* __restrict__ eb1,
               const float* __restrict__ eW2, const float* __restrict__ eb2,
               const float* __restrict__ vW1, const float* __restrict__ vb1,
               const float* __restrict__ vW2, const float* __restrict__ vb2,
               float* __restrict__ out, int N) {
    extern __shared__ char smemc[];
    const uint32_t sb = smem_u32(smemc);
    float* Ysm  = reinterpret_cast<float*>(smemc + YSM_OFF);
    float* parf = reinterpret_cast<float*>(smemc + PAR_OFF);

    const int tid = threadIdx.x;
    const int wid = tid >> 5;
    const int lane = tid & 31;
    const int nodeBase = blockIdx.x * 128;

    // warp tiling: warp w covers m rows [(w&3)*32, +32), n cols [(w>>2)*64, +64)
    const int m0w = (wid & 3) * 32;
    const int n0w = (wid >> 2) * 64;

    // ---- preload layer-2 params ----
    const float* b1s[4] = {mb1, ib1, eb1, vb1};
    for (int i = tid; i < 512; i += 256) parf[i] = b1s[i >> 7][i & 127];
    for (int i = tid; i < 128; i += 256) {
        parf[512 + i]  = mW2[i];
        parf[640 + i]  = iW2[i];
        parf[1152 + i] = vW2[i];
    }
    for (int i = tid; i < 384; i += 256) parf[768 + i] = eW2[i];
    if (tid == 0) {
        parf[1280] = mb2[0]; parf[1281] = ib2[0];
        parf[1282] = eb2[0]; parf[1283] = eb2[1]; parf[1284] = eb2[2];
        parf[1285] = vb2[0];
    }
    for (int i = tid; i < 128 * 8; i += 256) Ysm[i] = 0.f;

    // ---- load X tile [m][k], split hi/lo bf16 ----
    {
        const float4* Xg = reinterpret_cast<const float4*>(X);
        #pragma unroll
        for (int it = 0; it < 16; ++it) {
            int idx4 = tid + it * 256;           // 0..4095
            int row = idx4 >> 5;
            int c4  = idx4 & 31;
            int g = nodeBase + row;
            float4 v = make_float4(0.f, 0.f, 0.f, 0.f);
            if (g < N) v = Xg[g * 32 + c4];
            unsigned short h[4], l[4];
            #pragma unroll
            for (int d = 0; d < 4; ++d) {
                float x = (&v.x)[d];
                __nv_bfloat16 hb = __float2bfloat16(x);
                __nv_bfloat16 lb = __float2bfloat16(x - __bfloat162float(hb));
                h[d] = __bfloat16_as_ushort(hb);
                l[d] = __bfloat16_as_ushort(lb);
            }
            uint32_t off = (uint32_t)(row * PITCH + c4 * 4) * 2;
            *reinterpret_cast<uint2*>(smemc + XHI_OFF + off) =
                make_uint2((uint32_t)h[0] | ((uint32_t)h[1] << 16),
                           (uint32_t)h[2] | ((uint32_t)h[3] << 16));
            *reinterpret_cast<uint2*>(smemc + XLO_OFF + off) =
                make_uint2((uint32_t)l[0] | ((uint32_t)l[1] << 16),
                           (uint32_t)l[2] | ((uint32_t)l[3] << 16));
        }
    }

    const float* W1s[4]  = {mW1, iW1, eW1, vW1};
    const int    ncols[4] = {1, 1, 3, 1};
    const int    w2bs[4]  = {512, 640, 768, 1152};
    const int    slots[4] = {0, 1, 2, 5};

    for (int j = 0; j < 4; ++j) {
        __syncthreads();   // previous matrix done reading W tiles

        // ---- load W_j [k][n] (natural layout), split hi/lo ----
        const float4* Wg = reinterpret_cast<const float4*>(W1s[j]);
        #pragma unroll
        for (int it = 0; it < 16; ++it) {
            int idx4 = tid + it * 256;
            float4 w = Wg[idx4];
            int k  = idx4 >> 5;
            int n0 = (idx4 & 31) * 4;
            unsigned short h[4], l[4];
            #pragma unroll
            for (int d = 0; d < 4; ++d) {
                float x = (&w.x)[d];
                __nv_bfloat16 hb = __float2bfloat16(x);
                __nv_bfloat16 lb = __float2bfloat16(x - __bfloat162float(hb));
                h[d] = __bfloat16_as_ushort(hb);
                l[d] = __bfloat16_as_ushort(lb);
            }
            uint32_t off = (uint32_t)(k * PITCH + n0) * 2;
            *reinterpret_cast<uint2*>(smemc + WHI_OFF + off) =
                make_uint2((uint32_t)h[0] | ((uint32_t)h[1] << 16),
                           (uint32_t)h[2] | ((uint32_t)h[3] << 16));
            *reinterpret_cast<uint2*>(smemc + WLO_OFF + off) =
                make_uint2((uint32_t)l[0] | ((uint32_t)l[1] << 16),
                           (uint32_t)l[2] | ((uint32_t)l[3] << 16));
        }
        __syncthreads();

        // ---- GEMM: acc = Xhi*Whi + Xhi*Wlo + Xlo*Whi ----
        float acc[2][8][4];
        #pragma unroll
        for (int mt = 0; mt < 2; ++mt)
            #pragma unroll
            for (int nt = 0; nt < 8; ++nt)
                #pragma unroll
                for (int r = 0; r < 4; ++r) acc[mt][nt][r] = 0.f;

        const int ar = lane & 15;            // ldmatrix row supplier
        const int ac = (lane >> 4) * 8;
        for (int kc = 0; kc < 8; ++kc) {
            int k0 = kc * 16;
            uint32_t Ahi[2][4], Alo[2][4];
            #pragma unroll
            for (int mt = 0; mt < 2; ++mt) {
                uint32_t aoff = (uint32_t)((m0w + mt * 16 + ar) * PITCH + k0 + ac) * 2;
                ldsm_x4(Ahi[mt][0], Ahi[mt][1], Ahi[mt][2], Ahi[mt][3], sb + XHI_OFF + aoff);
                ldsm_x4(Alo[mt][0], Alo[mt][1], Alo[mt][2], Alo[mt][3], sb + XLO_OFF + aoff);
            }
            #pragma unroll
            for (int nt = 0; nt < 8; ++nt) {
                uint32_t boff = (uint32_t)((k0 + ar) * PITCH + n0w + nt * 8) * 2;
                uint32_t Bhi[2], Blo[2];
                ldsm_x2t(Bhi[0], Bhi[1], sb + WHI_OFF + boff);
                ldsm_x2t(Blo[0], Blo[1], sb + WLO_OFF + boff);
                #pragma unroll
                for (int mt = 0; mt < 2; ++mt) {
                    mma_bf16(acc[mt][nt], Ahi[mt], Bhi);
                    mma_bf16(acc[mt][nt], Ahi[mt], Blo);
                    mma_bf16(acc[mt][nt], Alo[mt], Bhi);
                }
            }
        }

        // ---- fused layer 2 epilogue ----
        // frag: c0,c1 -> (row g, col t*2 / t*2+1); c2,c3 -> (row g+8, ...)
        const int g = lane >> 2;
        const int t = lane & 3;
        const int nc = ncols[j], w2b = w2bs[j], sl = slots[j];
        #pragma unroll
        for (int mt = 0; mt < 2; ++mt) {
            #pragma unroll
            for (int half = 0; half < 2; ++half) {      // row g / g+8
                int node = m0w + mt * 16 + g + half * 8;
                float p0 = 0.f, p1 = 0.f, p2 = 0.f;
                #pragma unroll
                for (int nt = 0; nt < 8; ++nt) {
                    #pragma unroll
                    for (int cc = 0; cc < 2; ++cc) {
                        int h = n0w + nt * 8 + t * 2 + cc;
                        float v = fmaxf(acc[mt][nt][half * 2 + cc] + parf[j * 128 + h], 0.f);
                        p0 = fmaf(v, parf[w2b + h * nc + 0], p0);
                        if (nc == 3) {
                            p1 = fmaf(v, parf[w2b + h * 3 + 1], p1);
                            p2 = fmaf(v, parf[w2b + h * 3 + 2], p2);
                        }
                    }
                }
                atomicAdd(&Ysm[node * 8 + sl], p0);
                if (nc == 3) {
                    atomicAdd(&Ysm[node * 8 + sl + 1], p1);
                    atomicAdd(&Ysm[node * 8 + sl + 2], p2);
                }
            }
        }
    }
    __syncthreads();

    // ---- combine ----
    if (tid < 128) {
        int g = nodeBase + tid;
        if (g < N) {
            float invm = Ysm[tid * 8 + 0] + parf[1280];
            float invi = Ysm[tid * 8 + 1] + parf[1281];
            float e0 = Ysm[tid * 8 + 2] + parf[1282];
            float e1 = Ysm[tid * 8 + 3] + parf[1283];
            float e2 = Ysm[tid * 8 + 4] + parf[1284];
            float vs = Ysm[tid * 8 + 5] + parf[1285];

            float4 F = *reinterpret_cast<float4*>(&g_facc[g * 4]);
            float4 T = *reinterpret_cast<float4*>(&g_tacc[g * 4]);
            float4 C = *reinterpret_cast<float4*>(&g_cacc[g * 4]);
            float cnt = fmaxf(F.w, 1.0f);
            float inv_cnt = 1.0f / cnt;

            float vx = vel[g * 3 + 0], vy = vel[g * 3 + 1], vz = vel[g * 3 + 2];
            int N3 = N * 3;
            out[g * 3 + 0] = invm * F.x;
            out[g * 3 + 1] = invm * F.y;
            out[g * 3 + 2] = invm * F.z;
            out[N3 + g * 3 + 0] = invi * T.x;
            out[N3 + g * 3 + 1] = invi * T.y;
            out[N3 + g * 3 + 2] = invi * T.z;
            out[2 * N3 + g * 3 + 0] = (vx + e0) * vs + C.x * inv_cnt;
            out[2 * N3 + g * 3 + 1] = (vy + e1) * vs + C.y * inv_cnt;
            out[2 * N3 + g * 3 + 2] = (vz + e2) * vs + C.z * inv_cnt;
        }
    }
}

// ---------------------------------------------------------------------------
extern "C" void kernel_launch(void* const* d_in, const int* in_sizes, int n_in,
                              void* d_out, int out_size) {
    const int*   edge_index = (const int*)  d_in[0];
    const float* node_latent= (const float*)d_in[1];
    const float* vel        = (const float*)d_in[2];
    const float* ef         = (const float*)d_in[3];
    const float* et         = (const float*)d_in[4];
    const float* ec         = (const float*)d_in[5];
    const float* mW1 = (const float*)d_in[6];  const float* mb1 = (const float*)d_in[7];
    const float* mW2 = (const float*)d_in[8];  const float* mb2 = (const float*)d_in[9];
    const float* iW1 = (const float*)d_in[10]; const float* ib1 = (const float*)d_in[11];
    const float* iW2 = (const float*)d_in[12]; const float* ib2 = (const float*)d_in[13];
    const float* eW1 = (const float*)d_in[14]; const float* eb1 = (const float*)d_in[15];
    const float* eW2 = (const float*)d_in[16]; const float* eb2 = (const float*)d_in[17];
    const float* vW1 = (const float*)d_in[18]; const float* vb1 = (const float*)d_in[19];
    const float* vW2 = (const float*)d_in[20]; const float* vb2 = (const float*)d_in[21];
    float* out = (float*)d_out;

    int E = in_sizes[0] / 2;
    int N = in_sizes[1] / 128;

    zero_kernel<<<(N + 255) / 256, 256>>>(N);
    scatter_kernel<<<(E + 255) / 256, 256>>>(edge_index, ef, et, ec, E);

    cudaFuncSetAttribute(mlp_mma_kernel,
                         cudaFuncAttributeMaxDynamicSharedMemorySize, SMEM_TOTAL);
    mlp_mma_kernel<<<(N + 127) / 128, 256, SMEM_TOTAL>>>(
        node_latent, vel,
        mW1, mb1, mW2, mb2,
        iW1, ib1, iW2, ib2,
        eW1, eb1, eW2, eb2,
        vW1, vb1, vW2, vb2,
        out, N);
}